// round 4
// baseline (speedup 1.0000x reference)
#include <cuda_runtime.h>
#include <math.h>

// ---------------------------------------------------------------------------
// Problem constants
// ---------------------------------------------------------------------------
#define BB   2
#define SS   2048
#define DD   768
#define HH   12
#define DHH  64
#define FF   3072
#define VV   16384
#define NBK  64      // number of buckets (argmax over 2*32)
#define NROT 32      // NB/2
#define CC   64      // chunk length
#define NCC  32      // chunks per sequence  (SS/CC)
#define LL   2
#define MM   (BB*SS) // 4096 rows

// ---------------------------------------------------------------------------
// Accurate math helpers, immune to --use_fast_math:
//  - exp_acc: Cody-Waite range reduction + degree-6 Horner, ~1 ulp
//  - tanh_acc: via exp_acc and correctly-rounded division
// ---------------------------------------------------------------------------
__device__ __forceinline__ float exp_acc(float x)
{
    if (x < -87.0f) return 0.0f;                 // underflow (mask values)
    float n = rintf(x * 1.4426950408889634f);
    float r = __fmaf_rn(n, -0.693147182464599609375f, x);   // ln2_hi
    r = __fmaf_rn(n, 1.9046542121259063e-9f, r);            // -(ln2_lo)
    float p = 1.3888888888888889e-3f;                        // 1/720
    p = __fmaf_rn(p, r, 8.3333333333333332e-3f);             // 1/120
    p = __fmaf_rn(p, r, 4.1666666666666664e-2f);             // 1/24
    p = __fmaf_rn(p, r, 1.6666666666666666e-1f);             // 1/6
    p = __fmaf_rn(p, r, 0.5f);
    p = __fmaf_rn(p, r, 1.0f);
    p = __fmaf_rn(p, r, 1.0f);
    float sc = __int_as_float(((int)n + 127) << 23);
    return p * sc;
}

__device__ __forceinline__ float tanh_acc(float z)
{
    float az = fabsf(z);
    float t  = exp_acc(-2.0f * az);
    float th = __fdiv_rn(1.0f - t, 1.0f + t);
    return copysignf(th, z);
}

// ---------------------------------------------------------------------------
// Scratch (static device globals; no runtime allocation allowed)
// ---------------------------------------------------------------------------
__device__ float g_x  [BB*SS*DD];
__device__ float g_h  [BB*SS*DD];
__device__ float g_qk [BB*SS*DD];
__device__ float g_v  [BB*SS*DD];
__device__ float g_ao [BB*SS*DD];
__device__ float g_ffn[BB*SS*FF];
__device__ float g_sqk [BB*HH*SS*DHH];
__device__ float g_skey[BB*HH*SS*DHH];
__device__ float g_sv  [BB*HH*SS*DHH];
__device__ int   g_buckets[BB*HH*SS];
__device__ int   g_order  [BB*HH*SS];
__device__ int   g_sb[BB*HH*SS];
__device__ int   g_sm[BB*HH*SS];
__device__ int   g_si[BB*HH*SS];

// ---------------------------------------------------------------------------
// Embedding: x = emb[ids] + pos
// ---------------------------------------------------------------------------
__global__ void k_embed(const int* __restrict__ ids,
                        const float* __restrict__ emb,
                        const float* __restrict__ pos)
{
    int row = blockIdx.x;               // 0..MM-1
    int s   = row % SS;
    int id  = ids[row];
    const float* e = emb + (size_t)id * DD;
    const float* p = pos + (size_t)s  * DD;
    float* xo = g_x + (size_t)row * DD;
    for (int j = threadIdx.x; j < DD; j += blockDim.x)
        xo[j] = e[j] + p[j];
}

// ---------------------------------------------------------------------------
// LayerNorm (eps = 1e-12), one block (256 thr) per row of 768
// ---------------------------------------------------------------------------
__global__ void k_ln(const float* __restrict__ in, float* __restrict__ out,
                     const float* __restrict__ gg, const float* __restrict__ bb)
{
    int row = blockIdx.x;
    int tid = threadIdx.x;
    const float* x = in + (size_t)row * DD;
    __shared__ float red[32];

    float v0 = x[tid], v1 = x[tid + 256], v2 = x[tid + 512];

    float s = v0 + v1 + v2;
    #pragma unroll
    for (int o = 16; o; o >>= 1) s += __shfl_xor_sync(0xffffffffu, s, o);
    if ((tid & 31) == 0) red[tid >> 5] = s;
    __syncthreads();
    if (tid < 32) {
        float t = (tid < 8) ? red[tid] : 0.f;
        #pragma unroll
        for (int o = 4; o; o >>= 1) t += __shfl_xor_sync(0xffffffffu, t, o);
        if (tid == 0) red[0] = t;
    }
    __syncthreads();
    float mean = red[0] * (1.0f / (float)DD);
    __syncthreads();

    float d0 = v0 - mean, d1 = v1 - mean, d2 = v2 - mean;
    float q = d0 * d0 + d1 * d1 + d2 * d2;
    #pragma unroll
    for (int o = 16; o; o >>= 1) q += __shfl_xor_sync(0xffffffffu, q, o);
    if ((tid & 31) == 0) red[tid >> 5] = q;
    __syncthreads();
    if (tid < 32) {
        float t = (tid < 8) ? red[tid] : 0.f;
        #pragma unroll
        for (int o = 4; o; o >>= 1) t += __shfl_xor_sync(0xffffffffu, t, o);
        if (tid == 0) red[0] = t;
    }
    __syncthreads();
    float var = red[0] * (1.0f / (float)DD);
    float r = __frsqrt_rn(var + 1e-12f);

    float* o0 = out + (size_t)row * DD;
    o0[tid]       = d0 * r * gg[tid]       + bb[tid];
    o0[tid + 256] = d1 * r * gg[tid + 256] + bb[tid + 256];
    o0[tid + 512] = d2 * r * gg[tid + 512] + bb[tid + 512];
}

// ---------------------------------------------------------------------------
// Generic SGEMM: C[M,N] = A[M,K] @ B[K,N]  (+ epilogue)
// 128x128 tile, BK=8, 256 threads, 8x8 per thread. Two-level accumulation:
// exact-ish 8-term tile partial, then one add per k0-tile (low noise).
// ---------------------------------------------------------------------------
#define EPI_NONE      0
#define EPI_BIAS      1
#define EPI_BIAS_GELU 2
#define EPI_RES       3
#define EPI_BIAS_RES  4

__device__ __forceinline__ float gelu_tanh(float x)
{
    float x3 = x * x * x;
    return 0.5f * x * (1.0f + tanh_acc(0.7978845608028654f * (x + 0.044715f * x3)));
}

template <int EPI>
__global__ void __launch_bounds__(256) k_gemm(
                       const float* __restrict__ A, const float* __restrict__ Bm,
                       const float* __restrict__ bias, const float* __restrict__ res,
                       float* __restrict__ Cm, int M, int N, int K)
{
    __shared__ float As[8][128];
    __shared__ float Bs[8][128];

    int tid = threadIdx.x;
    int bx = blockIdx.x, by = blockIdx.y;

    const float* Ap = A  + (size_t)(by * 128) * K;
    const float* Bp = Bm + (size_t)(bx * 128);

    int arow = tid >> 1;          // 0..127
    int acol = (tid & 1) * 4;     // 0 or 4
    int brow = tid >> 5;          // 0..7
    int bcol = (tid & 31) * 4;    // 0..124

    int ty = tid >> 4, tx = tid & 15;

    float acc[8][8];
    #pragma unroll
    for (int i = 0; i < 8; i++)
        #pragma unroll
        for (int j = 0; j < 8; j++) acc[i][j] = 0.f;

    for (int k0 = 0; k0 < K; k0 += 8) {
        float4 av = *(const float4*)(Ap + (size_t)arow * K + k0 + acol);
        As[acol + 0][arow] = av.x;
        As[acol + 1][arow] = av.y;
        As[acol + 2][arow] = av.z;
        As[acol + 3][arow] = av.w;
        float4 bv = *(const float4*)(Bp + (size_t)(k0 + brow) * N + bcol);
        *(float4*)&Bs[brow][bcol] = bv;
        __syncthreads();

        float part[8][8];
        #pragma unroll
        for (int i = 0; i < 8; i++)
            #pragma unroll
            for (int j = 0; j < 8; j++) part[i][j] = 0.f;

        #pragma unroll
        for (int kk = 0; kk < 8; kk++) {
            float ra[8], rb[8];
            *(float4*)&ra[0] = *(const float4*)&As[kk][ty * 8];
            *(float4*)&ra[4] = *(const float4*)&As[kk][ty * 8 + 4];
            *(float4*)&rb[0] = *(const float4*)&Bs[kk][tx * 8];
            *(float4*)&rb[4] = *(const float4*)&Bs[kk][tx * 8 + 4];
            #pragma unroll
            for (int i = 0; i < 8; i++)
                #pragma unroll
                for (int j = 0; j < 8; j++)
                    part[i][j] += ra[i] * rb[j];
        }
        #pragma unroll
        for (int i = 0; i < 8; i++)
            #pragma unroll
            for (int j = 0; j < 8; j++)
                acc[i][j] += part[i][j];
        __syncthreads();
    }

    #pragma unroll
    for (int i = 0; i < 8; i++) {
        int row = by * 128 + ty * 8 + i;
        #pragma unroll
        for (int j = 0; j < 8; j++) {
            int col = bx * 128 + tx * 8 + j;
            float v = acc[i][j];
            if (EPI == EPI_BIAS || EPI == EPI_BIAS_GELU || EPI == EPI_BIAS_RES)
                v += bias[col];
            if (EPI == EPI_BIAS_GELU)
                v = gelu_tanh(v);
            if (EPI == EPI_RES || EPI == EPI_BIAS_RES)
                v += res[(size_t)row * N + col];
            Cm[(size_t)row * N + col] = v;
        }
    }
}

// ---------------------------------------------------------------------------
// LSH hashing: one warp per (b,h,s) position. Kahan-compensated dot so the
// bucket decision carries ~1e-8 noise (below the reference's own rounding).
// bucket = argmax concat(rotated,-rotated), first-occurrence tie-break.
// ---------------------------------------------------------------------------
__global__ void k_hash(const float* __restrict__ rot)
{
    int lane = threadIdx.x & 31;
    int wid  = blockIdx.x * (blockDim.x >> 5) + (threadIdx.x >> 5);
    if (wid >= BB * HH * SS) return;
    int b = wid / (HH * SS);
    int r = wid % (HH * SS);
    int h = r / SS;
    int s = r % SS;

    const float* q  = g_qk + ((size_t)(b * SS + s)) * DD + h * DHH;
    const float* rr = rot + (size_t)h * DHH * NROT;

    float sum = 0.f, comp = 0.f;
    #pragma unroll
    for (int d = 0; d < DHH; d++) {
        float p = __fmul_rn(q[d], rr[d * NROT + lane]);
        float y = __fsub_rn(p, comp);
        float t = __fadd_rn(sum, y);
        comp = __fsub_rn(__fsub_rn(t, sum), y);
        sum = t;
    }
    float acc = sum;

    float v; int idx;
    if (acc >= -acc) { v = acc;  idx = lane; }
    else             { v = -acc; idx = lane + NROT; }

    #pragma unroll
    for (int o = 16; o; o >>= 1) {
        float v2 = __shfl_down_sync(0xffffffffu, v, o);
        int   i2 = __shfl_down_sync(0xffffffffu, idx, o);
        if (v2 > v || (v2 == v && i2 < idx)) { v = v2; idx = i2; }
    }
    if (lane == 0) g_buckets[wid] = idx;
}

// ---------------------------------------------------------------------------
// Stable counting sort by bucket per (b,h): equivalent to
// argsort(bucket*S + pos).  One block of 64 threads per (b,h).
// ---------------------------------------------------------------------------
__global__ void k_sort()
{
    int bh = blockIdx.x;                 // 0..BB*HH-1
    const int* bk = g_buckets + (size_t)bh * SS;
    int* ord = g_order + (size_t)bh * SS;
    __shared__ int cnt[NBK], off[NBK];
    int t = threadIdx.x;                 // 0..63  == bucket id

    int c = 0;
    for (int s = 0; s < SS; s++)
        if (bk[s] == t) c++;
    cnt[t] = c;
    __syncthreads();
    if (t == 0) {
        int a = 0;
        for (int i = 0; i < NBK; i++) { off[i] = a; a += cnt[i]; }
    }
    __syncthreads();
    int o = off[t];
    for (int s = 0; s < SS; s++)
        if (bk[s] == t) ord[o++] = s;
}

// ---------------------------------------------------------------------------
// Gather into sorted order + key L2-normalization (exact fp32).
// One warp per position.
// ---------------------------------------------------------------------------
__global__ void k_gather(const int* __restrict__ mask)
{
    int lane = threadIdx.x & 31;
    int wid  = blockIdx.x * (blockDim.x >> 5) + (threadIdx.x >> 5);
    if (wid >= BB * HH * SS) return;
    int b = wid / (HH * SS);
    int r = wid % (HH * SS);
    int h = r / SS;

    int j = g_order[wid];
    const float* qrow = g_qk + ((size_t)(b * SS + j)) * DD + h * DHH;
    const float* vrow = g_v  + ((size_t)(b * SS + j)) * DD + h * DHH;

    float a0 = qrow[lane], a1 = qrow[lane + 32];
    float ss = a0 * a0 + a1 * a1;
    #pragma unroll
    for (int o = 16; o; o >>= 1) ss += __shfl_xor_sync(0xffffffffu, ss, o);
    float inv = __fdiv_rn(1.f, __fsqrt_rn(ss) + 1e-6f);

    size_t base = (size_t)wid * DHH;
    g_sqk [base + lane]      = a0;
    g_sqk [base + lane + 32] = a1;
    g_skey[base + lane]      = a0 * inv;
    g_skey[base + lane + 32] = a1 * inv;
    g_sv  [base + lane]      = vrow[lane];
    g_sv  [base + lane + 32] = vrow[lane + 32];

    if (lane == 0) {
        g_sb[wid] = g_buckets[(size_t)(b * HH + h) * SS + j];
        g_sm[wid] = mask[b * SS + j];
        g_si[wid] = j;
    }
}

// ---------------------------------------------------------------------------
// Chunked LSH attention: one block per (b,h,chunk). Keys/values look back
// one chunk (wraps). Masks + softmax + AV + unsort-scatter fused. Exact fp32;
// exp/div via accurate helpers (fast-math-proof).
// ---------------------------------------------------------------------------
#define ATTN_F (64*64 + 128*65 + 128*65 + 64*128)
#define ATTN_I (64 + 128 + 128 + 64 + 128)
#define ATTN_SMEM (ATTN_F*4 + ATTN_I*4)

__global__ void k_attn()
{
    extern __shared__ float smf[];
    float* qs = smf;                      // [64][64]
    float* ks = qs + 64 * 64;             // [128][65]
    float* vs = ks + 128 * 65;            // [128][65]
    float* ds = vs + 128 * 65;            // [64][128]
    int* ib = (int*)(ds + 64 * 128);
    int* bc = ib;            // [64]
    int* be = bc + 64;       // [128]
    int* me = be + 128;      // [128]
    int* ic = me + 128;      // [64]
    int* ie = ic + 64;       // [128]

    int n = blockIdx.x, h = blockIdx.y, b = blockIdx.z;
    int tid = threadIdx.x;                // 256 threads
    size_t base_bh = (size_t)(b * HH + h) * SS;
    int prev = (n + NCC - 1) % NCC;

    for (int idx = tid; idx < 64 * 64; idx += 256) {
        int c = idx >> 6, d = idx & 63;
        qs[idx] = g_sqk[(base_bh + n * CC + c) * DHH + d];
    }
    for (int idx = tid; idx < 128 * 64; idx += 256) {
        int k = idx >> 6, d = idx & 63;
        int chunk = (k < 64) ? prev : n;
        int rrow  = (k < 64) ? k : (k - 64);
        size_t src = (base_bh + chunk * CC + rrow) * DHH + d;
        ks[k * 65 + d] = g_skey[src];
        vs[k * 65 + d] = g_sv[src];
    }
    for (int idx = tid; idx < 64; idx += 256) {
        bc[idx] = g_sb[base_bh + n * CC + idx];
        ic[idx] = g_si[base_bh + n * CC + idx];
    }
    for (int idx = tid; idx < 128; idx += 256) {
        int chunk = (idx < 64) ? prev : n;
        int rrow  = (idx < 64) ? idx : (idx - 64);
        be[idx] = g_sb[base_bh + chunk * CC + rrow];
        me[idx] = g_sm[base_bh + chunk * CC + rrow];
        ie[idx] = g_si[base_bh + chunk * CC + rrow];
    }
    __syncthreads();

    // dots + masks
    for (int idx = tid; idx < 64 * 128; idx += 256) {
        int c = idx >> 7, k = idx & 127;
        float acc = 0.f;
        #pragma unroll
        for (int d = 0; d < 64; d++)
            acc += qs[c * 64 + d] * ks[k * 65 + d];
        acc *= 0.125f;                          // 1/sqrt(64), exact
        if (bc[c] != be[k] || me[k] <= 0) acc = -1e9f;
        if (ic[c] == ie[k])               acc = -1e5f;
        ds[c * 128 + k] = acc;
    }
    __syncthreads();

    // row softmax: 8 warps handle 64 rows
    int warp = tid >> 5, lane = tid & 31;
    for (int c = warp; c < 64; c += 8) {
        float v0 = ds[c * 128 + lane];
        float v1 = ds[c * 128 + lane + 32];
        float v2 = ds[c * 128 + lane + 64];
        float v3 = ds[c * 128 + lane + 96];
        float mx = fmaxf(fmaxf(v0, v1), fmaxf(v2, v3));
        #pragma unroll
        for (int o = 16; o; o >>= 1) mx = fmaxf(mx, __shfl_xor_sync(0xffffffffu, mx, o));
        float e0 = exp_acc(v0 - mx), e1 = exp_acc(v1 - mx);
        float e2 = exp_acc(v2 - mx), e3 = exp_acc(v3 - mx);
        float sm = e0 + e1 + e2 + e3;
        #pragma unroll
        for (int o = 16; o; o >>= 1) sm += __shfl_xor_sync(0xffffffffu, sm, o);
        ds[c * 128 + lane]      = __fdiv_rn(e0, sm);
        ds[c * 128 + lane + 32] = __fdiv_rn(e1, sm);
        ds[c * 128 + lane + 64] = __fdiv_rn(e2, sm);
        ds[c * 128 + lane + 96] = __fdiv_rn(e3, sm);
    }
    __syncthreads();

    // out = attn @ ve, scattered back to original positions (fused unsort)
    for (int idx = tid; idx < 64 * 64; idx += 256) {
        int c = idx >> 6, d = idx & 63;
        float acc = 0.f;
        #pragma unroll
        for (int k = 0; k < 128; k++)
            acc += ds[c * 128 + k] * vs[k * 65 + d];
        int sdst = ic[c];
        g_ao[((size_t)(b * SS + sdst)) * DD + h * DHH + d] = acc;
    }
}

// ---------------------------------------------------------------------------
// Launch
// ---------------------------------------------------------------------------
extern "C" void kernel_launch(void* const* d_in, const int* in_sizes, int n_in,
                              void* d_out, int out_size)
{
    const int*   ids  = (const int*)  d_in[0];
    const int*   mask = (const int*)  d_in[1];
    const float* emb  = (const float*)d_in[2];
    const float* pos  = (const float*)d_in[3];
    const float* rot  = (const float*)d_in[4];
    const float* Wqk  = (const float*)d_in[5];
    const float* Wv   = (const float*)d_in[6];
    const float* Wo   = (const float*)d_in[7];
    const float* ln1g = (const float*)d_in[8];
    const float* ln1b = (const float*)d_in[9];
    const float* ln2g = (const float*)d_in[10];
    const float* ln2b = (const float*)d_in[11];
    const float* W1   = (const float*)d_in[12];
    const float* b1   = (const float*)d_in[13];
    const float* W2   = (const float*)d_in[14];
    const float* b2   = (const float*)d_in[15];
    const float* lnfg = (const float*)d_in[16];
    const float* lnfb = (const float*)d_in[17];
    const float* Wlm  = (const float*)d_in[18];
    const float* blm  = (const float*)d_in[19];
    float* out = (float*)d_out;

    float *x, *h, *qk, *v, *ao, *ffn;
    cudaGetSymbolAddress((void**)&x,   g_x);
    cudaGetSymbolAddress((void**)&h,   g_h);
    cudaGetSymbolAddress((void**)&qk,  g_qk);
    cudaGetSymbolAddress((void**)&v,   g_v);
    cudaGetSymbolAddress((void**)&ao,  g_ao);
    cudaGetSymbolAddress((void**)&ffn, g_ffn);

    cudaFuncSetAttribute(k_attn, cudaFuncAttributeMaxDynamicSharedMemorySize, ATTN_SMEM);

    k_embed<<<MM, 256>>>(ids, emb, pos);

    dim3 gD (DD / 128,  MM / 128);
    dim3 gF (FF / 128,  MM / 128);
    dim3 gV (VV / 128,  MM / 128);

    for (int l = 0; l < LL; l++) {
        k_ln<<<MM, 256>>>(x, h, ln1g + l * DD, ln1b + l * DD);

        k_gemm<EPI_NONE><<<gD, 256>>>(h, Wqk + (size_t)l * DD * DD, nullptr, nullptr, qk, MM, DD, DD);
        k_gemm<EPI_NONE><<<gD, 256>>>(h, Wv  + (size_t)l * DD * DD, nullptr, nullptr, v,  MM, DD, DD);

        k_hash<<<(BB * HH * SS) / 4, 128>>>(rot + (size_t)l * HH * DHH * NROT);
        k_sort<<<BB * HH, NBK>>>();
        k_gather<<<(BB * HH * SS) / 4, 128>>>(mask);

        k_attn<<<dim3(NCC, HH, BB), 256, ATTN_SMEM>>>();

        k_gemm<EPI_RES><<<gD, 256>>>(ao, Wo + (size_t)l * DD * DD, nullptr, x, x, MM, DD, DD);

        k_ln<<<MM, 256>>>(x, h, ln2g + l * DD, ln2b + l * DD);
        k_gemm<EPI_BIAS_GELU><<<gF, 256>>>(h, W1 + (size_t)l * DD * FF, b1 + (size_t)l * FF, nullptr, ffn, MM, FF, DD);
        k_gemm<EPI_BIAS_RES><<<gD, 256>>>(ffn, W2 + (size_t)l * FF * DD, b2 + (size_t)l * DD, x, x, MM, DD, FF);
    }

    k_ln<<<MM, 256>>>(x, h, lnfg, lnfb);
    k_gemm<EPI_BIAS><<<gV, 256>>>(h, Wlm, blm, nullptr, out, MM, VV, DD);
}

// round 7
// speedup vs baseline: 1.0917x; 1.0917x over previous
#include <cuda_runtime.h>
#include <math.h>
#include <stdint.h>

// ---------------------------------------------------------------------------
// Problem constants
// ---------------------------------------------------------------------------
#define BB   2
#define SS   2048
#define DD   768
#define HH   12
#define DHH  64
#define FF   3072
#define VV   16384
#define NBK  64      // number of buckets (argmax over 2*32)
#define NROT 32      // NB/2
#define CC   64      // chunk length
#define NCC  32      // chunks per sequence  (SS/CC)
#define LL   2
#define MM   (BB*SS) // 4096 rows

// ---------------------------------------------------------------------------
// Accurate math helpers, immune to --use_fast_math:
//  - exp_acc: Cody-Waite range reduction + degree-6 Horner, ~1 ulp
//  - tanh_acc: via exp_acc and correctly-rounded division
// ---------------------------------------------------------------------------
__device__ __forceinline__ float exp_acc(float x)
{
    if (x < -87.0f) return 0.0f;                 // underflow (mask values)
    float n = rintf(x * 1.4426950408889634f);
    float r = __fmaf_rn(n, -0.693147182464599609375f, x);   // ln2_hi
    r = __fmaf_rn(n, 1.9046542121259063e-9f, r);            // -(ln2_lo)
    float p = 1.3888888888888889e-3f;                        // 1/720
    p = __fmaf_rn(p, r, 8.3333333333333332e-3f);             // 1/120
    p = __fmaf_rn(p, r, 4.1666666666666664e-2f);             // 1/24
    p = __fmaf_rn(p, r, 1.6666666666666666e-1f);             // 1/6
    p = __fmaf_rn(p, r, 0.5f);
    p = __fmaf_rn(p, r, 1.0f);
    p = __fmaf_rn(p, r, 1.0f);
    float sc = __int_as_float(((int)n + 127) << 23);
    return p * sc;
}

__device__ __forceinline__ float tanh_acc(float z)
{
    float az = fabsf(z);
    float t  = exp_acc(-2.0f * az);
    float th = __fdiv_rn(1.0f - t, 1.0f + t);
    return copysignf(th, z);
}

// TF32 round-to-nearest (for the tensor-core path only; bucket path untouched)
__device__ __forceinline__ float tf32r(float x)
{
    unsigned u;
    asm("cvt.rna.tf32.f32 %0, %1;" : "=r"(u) : "f"(x));
    return __uint_as_float(u);
}

// ---------------------------------------------------------------------------
// Scratch (static device globals; no runtime allocation allowed)
// ---------------------------------------------------------------------------
__device__ float g_x  [BB*SS*DD];
__device__ float g_h  [BB*SS*DD];
__device__ float g_qk [BB*SS*DD];
__device__ float g_v  [BB*SS*DD];
__device__ float g_ao [BB*SS*DD];
__device__ float g_ffn[BB*SS*FF];
__device__ float g_sqk [BB*HH*SS*DHH];
__device__ float g_skey[BB*HH*SS*DHH];
__device__ float g_sv  [BB*HH*SS*DHH];
__device__ int   g_buckets[BB*HH*SS];
__device__ int   g_order  [BB*HH*SS];
__device__ int   g_sb[BB*HH*SS];
__device__ int   g_sm[BB*HH*SS];
__device__ int   g_si[BB*HH*SS];

// ---------------------------------------------------------------------------
// Embedding: x = emb[ids] + pos
// ---------------------------------------------------------------------------
__global__ void k_embed(const int* __restrict__ ids,
                        const float* __restrict__ emb,
                        const float* __restrict__ pos)
{
    int row = blockIdx.x;               // 0..MM-1
    int s   = row % SS;
    int id  = ids[row];
    const float* e = emb + (size_t)id * DD;
    const float* p = pos + (size_t)s  * DD;
    float* xo = g_x + (size_t)row * DD;
    for (int j = threadIdx.x; j < DD; j += blockDim.x)
        xo[j] = e[j] + p[j];
}

// ---------------------------------------------------------------------------
// LayerNorm (eps = 1e-12), one block (256 thr) per row of 768
// ---------------------------------------------------------------------------
__global__ void k_ln(const float* __restrict__ in, float* __restrict__ out,
                     const float* __restrict__ gg, const float* __restrict__ bb)
{
    int row = blockIdx.x;
    int tid = threadIdx.x;
    const float* x = in + (size_t)row * DD;
    __shared__ float red[32];

    float v0 = x[tid], v1 = x[tid + 256], v2 = x[tid + 512];

    float s = v0 + v1 + v2;
    #pragma unroll
    for (int o = 16; o; o >>= 1) s += __shfl_xor_sync(0xffffffffu, s, o);
    if ((tid & 31) == 0) red[tid >> 5] = s;
    __syncthreads();
    if (tid < 32) {
        float t = (tid < 8) ? red[tid] : 0.f;
        #pragma unroll
        for (int o = 4; o; o >>= 1) t += __shfl_xor_sync(0xffffffffu, t, o);
        if (tid == 0) red[0] = t;
    }
    __syncthreads();
    float mean = red[0] * (1.0f / (float)DD);
    __syncthreads();

    float d0 = v0 - mean, d1 = v1 - mean, d2 = v2 - mean;
    float q = d0 * d0 + d1 * d1 + d2 * d2;
    #pragma unroll
    for (int o = 16; o; o >>= 1) q += __shfl_xor_sync(0xffffffffu, q, o);
    if ((tid & 31) == 0) red[tid >> 5] = q;
    __syncthreads();
    if (tid < 32) {
        float t = (tid < 8) ? red[tid] : 0.f;
        #pragma unroll
        for (int o = 4; o; o >>= 1) t += __shfl_xor_sync(0xffffffffu, t, o);
        if (tid == 0) red[0] = t;
    }
    __syncthreads();
    float var = red[0] * (1.0f / (float)DD);
    float r = __frsqrt_rn(var + 1e-12f);

    float* o0 = out + (size_t)row * DD;
    o0[tid]       = d0 * r * gg[tid]       + bb[tid];
    o0[tid + 256] = d1 * r * gg[tid + 256] + bb[tid + 256];
    o0[tid + 512] = d2 * r * gg[tid + 512] + bb[tid + 512];
}

// ---------------------------------------------------------------------------
// Epilogue modes
// ---------------------------------------------------------------------------
#define EPI_NONE      0
#define EPI_BIAS      1
#define EPI_BIAS_GELU 2
#define EPI_RES       3
#define EPI_BIAS_RES  4

__device__ __forceinline__ float gelu_tanh(float x)
{
    float x3 = x * x * x;
    return 0.5f * x * (1.0f + tanh_acc(0.7978845608028654f * (x + 0.044715f * x3)));
}

// ---------------------------------------------------------------------------
// EXACT SGEMM (bucket-critical path) — numerics must stay BITWISE identical
// to round 4: 128x128 tile, BK=8, two-level accumulation. DO NOT TOUCH.
// ---------------------------------------------------------------------------
template <int EPI>
__global__ void __launch_bounds__(256) k_gemm(
                       const float* __restrict__ A, const float* __restrict__ Bm,
                       const float* __restrict__ bias, const float* __restrict__ res,
                       float* __restrict__ Cm, int M, int N, int K)
{
    __shared__ float As[8][128];
    __shared__ float Bs[8][128];

    int tid = threadIdx.x;
    int bx = blockIdx.x, by = blockIdx.y;

    const float* Ap = A  + (size_t)(by * 128) * K;
    const float* Bp = Bm + (size_t)(bx * 128);

    int arow = tid >> 1;          // 0..127
    int acol = (tid & 1) * 4;     // 0 or 4
    int brow = tid >> 5;          // 0..7
    int bcol = (tid & 31) * 4;    // 0..124

    int ty = tid >> 4, tx = tid & 15;

    float acc[8][8];
    #pragma unroll
    for (int i = 0; i < 8; i++)
        #pragma unroll
        for (int j = 0; j < 8; j++) acc[i][j] = 0.f;

    for (int k0 = 0; k0 < K; k0 += 8) {
        float4 av = *(const float4*)(Ap + (size_t)arow * K + k0 + acol);
        As[acol + 0][arow] = av.x;
        As[acol + 1][arow] = av.y;
        As[acol + 2][arow] = av.z;
        As[acol + 3][arow] = av.w;
        float4 bv = *(const float4*)(Bp + (size_t)(k0 + brow) * N + bcol);
        *(float4*)&Bs[brow][bcol] = bv;
        __syncthreads();

        float part[8][8];
        #pragma unroll
        for (int i = 0; i < 8; i++)
            #pragma unroll
            for (int j = 0; j < 8; j++) part[i][j] = 0.f;

        #pragma unroll
        for (int kk = 0; kk < 8; kk++) {
            float ra[8], rb[8];
            *(float4*)&ra[0] = *(const float4*)&As[kk][ty * 8];
            *(float4*)&ra[4] = *(const float4*)&As[kk][ty * 8 + 4];
            *(float4*)&rb[0] = *(const float4*)&Bs[kk][tx * 8];
            *(float4*)&rb[4] = *(const float4*)&Bs[kk][tx * 8 + 4];
            #pragma unroll
            for (int i = 0; i < 8; i++)
                #pragma unroll
                for (int j = 0; j < 8; j++)
                    part[i][j] += ra[i] * rb[j];
        }
        #pragma unroll
        for (int i = 0; i < 8; i++)
            #pragma unroll
            for (int j = 0; j < 8; j++)
                acc[i][j] += part[i][j];
        __syncthreads();
    }

    #pragma unroll
    for (int i = 0; i < 8; i++) {
        int row = by * 128 + ty * 8 + i;
        #pragma unroll
        for (int j = 0; j < 8; j++) {
            int col = bx * 128 + tx * 8 + j;
            float v = acc[i][j];
            if (EPI == EPI_BIAS || EPI == EPI_BIAS_GELU || EPI == EPI_BIAS_RES)
                v += bias[col];
            if (EPI == EPI_BIAS_GELU)
                v = gelu_tanh(v);
            if (EPI == EPI_RES || EPI == EPI_BIAS_RES)
                v += res[(size_t)row * N + col];
            Cm[(size_t)row * N + col] = v;
        }
    }
}

// ---------------------------------------------------------------------------
// FAST TENSOR-CORE GEMM (continuous path only): 3xTF32 fp32 emulation.
// C = Ahi*Bhi + Ahi*Blo + Alo*Bhi  via mma.sync.m16n8k8.tf32 (~1e-7 rel).
// 128x128x16 tile, 256 threads (8 warps in 2x4), fragment-layout smem so
// A-frags load with one LDS.128 and B-frags with one LDS.64, conflict-free.
// ---------------------------------------------------------------------------
__device__ __forceinline__ void mma_tf32(float* d, const uint32_t* a, const uint32_t* b)
{
    asm volatile(
        "mma.sync.aligned.m16n8k8.row.col.f32.tf32.tf32.f32 "
        "{%0,%1,%2,%3}, {%4,%5,%6,%7}, {%8,%9}, {%0,%1,%2,%3};\n"
        : "+f"(d[0]), "+f"(d[1]), "+f"(d[2]), "+f"(d[3])
        : "r"(a[0]), "r"(a[1]), "r"(a[2]), "r"(a[3]), "r"(b[0]), "r"(b[1]));
}

template <int EPI>
__global__ void __launch_bounds__(256) k_gemm_tf32(
                       const float* __restrict__ A, const float* __restrict__ Bm,
                       const float* __restrict__ bias, const float* __restrict__ res,
                       float* __restrict__ Cm, int M, int N, int K)
{
    // fragment-layout staging: A: [8 m-tiles][2 ksteps][32 lanes][4 regs]
    //                          B: [16 n-tiles][2 ksteps][32 lanes][2 regs]
    __shared__ __align__(16) float Ah[2048], Al[2048], Bh[2048], Bl[2048];

    int tid = threadIdx.x;
    int bx = blockIdx.x, by = blockIdx.y;
    int wid = tid >> 5, lane = tid & 31;
    int warp_m = wid & 1;           // 0..1 -> 64 rows each
    int warp_n = wid >> 1;          // 0..3 -> 32 cols each

    const float* Ap = A  + (size_t)(by * 128) * K;
    const float* Bp = Bm + (size_t)(bx * 128);

    float acc[4][4][4];
    #pragma unroll
    for (int i = 0; i < 4; i++)
        #pragma unroll
        for (int j = 0; j < 4; j++)
            #pragma unroll
            for (int r = 0; r < 4; r++) acc[i][j][r] = 0.f;

    for (int k0 = 0; k0 < K; k0 += 16) {
        // ---- stage A (128x16) into hi/lo fragment layout ----
        #pragma unroll
        for (int i = 0; i < 2; i++) {
            int idx  = tid * 2 + i;            // 0..511
            int row  = idx >> 2;               // 0..127
            int kc   = (idx & 3) * 4;          // 0,4,8,12
            float4 v = *(const float4*)(Ap + (size_t)row * K + k0 + kc);
            int r    = row & 15;
            int mt   = row >> 4;               // 0..7
            int ks   = kc >> 3;                // 0..1
            int kkb  = kc & 7;                 // 0 or 4
            int base = (mt * 2 + ks) * 128 + (r & 7) * 16 + (r >> 3) + 2 * (kkb >> 2);
            float vv[4] = {v.x, v.y, v.z, v.w};
            #pragma unroll
            for (int j = 0; j < 4; j++) {
                float hi = tf32r(vv[j]);
                Ah[base + j * 4] = hi;
                Al[base + j * 4] = tf32r(__fsub_rn(vv[j], hi));
            }
        }
        // ---- stage B (16x128) into hi/lo fragment layout ----
        #pragma unroll
        for (int i = 0; i < 2; i++) {
            int idx  = tid * 2 + i;            // 0..511
            int krow = idx >> 5;               // 0..15
            int n4   = (idx & 31) * 4;         // 0..124
            float4 v = *(const float4*)(Bp + (size_t)(k0 + krow) * N + n4);
            int ks   = krow >> 3;
            int kk   = krow & 7;
            int nt   = n4 >> 3;                // 0..15
            int nr   = n4 & 7;                 // 0 or 4
            int base = (nt * 2 + ks) * 64 + (nr * 4 + (kk & 3)) * 2 + (kk >> 2);
            float vv[4] = {v.x, v.y, v.z, v.w};
            #pragma unroll
            for (int j = 0; j < 4; j++) {
                float hi = tf32r(vv[j]);
                Bh[base + j * 8] = hi;
                Bl[base + j * 8] = tf32r(__fsub_rn(vv[j], hi));
            }
        }
        __syncthreads();

        // ---- compute: 2 ksteps of k=8 ----
        #pragma unroll
        for (int ks = 0; ks < 2; ks++) {
            uint32_t bh[4][2], bl[4][2];
            #pragma unroll
            for (int nj = 0; nj < 4; nj++) {
                int off = ((warp_n * 4 + nj) * 2 + ks) * 64 + lane * 2;
                *(uint2*)bh[nj] = *(const uint2*)(Bh + off);
                *(uint2*)bl[nj] = *(const uint2*)(Bl + off);
            }
            #pragma unroll
            for (int mi = 0; mi < 4; mi++) {
                uint32_t ah[4], al[4];
                int off = ((warp_m * 4 + mi) * 2 + ks) * 128 + lane * 4;
                *(uint4*)ah = *(const uint4*)(Ah + off);
                *(uint4*)al = *(const uint4*)(Al + off);
                #pragma unroll
                for (int nj = 0; nj < 4; nj++) {
                    mma_tf32(acc[mi][nj], ah, bl[nj]);   // hi*lo
                    mma_tf32(acc[mi][nj], al, bh[nj]);   // lo*hi
                    mma_tf32(acc[mi][nj], ah, bh[nj]);   // hi*hi
                }
            }
        }
        __syncthreads();
    }

    // ---- epilogue ----
    #pragma unroll
    for (int mi = 0; mi < 4; mi++) {
        int row0 = by * 128 + warp_m * 64 + mi * 16 + (lane >> 2);
        #pragma unroll
        for (int nj = 0; nj < 4; nj++) {
            int col0 = bx * 128 + warp_n * 32 + nj * 8 + (lane & 3) * 2;
            float v00 = acc[mi][nj][0], v01 = acc[mi][nj][1];
            float v10 = acc[mi][nj][2], v11 = acc[mi][nj][3];
            if (EPI == EPI_BIAS || EPI == EPI_BIAS_GELU || EPI == EPI_BIAS_RES) {
                float b0 = bias[col0], b1 = bias[col0 + 1];
                v00 += b0; v01 += b1; v10 += b0; v11 += b1;
            }
            if (EPI == EPI_BIAS_GELU) {
                v00 = gelu_tanh(v00); v01 = gelu_tanh(v01);
                v10 = gelu_tanh(v10); v11 = gelu_tanh(v11);
            }
            if (EPI == EPI_RES || EPI == EPI_BIAS_RES) {
                const float* r0 = res + (size_t)row0 * N + col0;
                const float* r1 = res + (size_t)(row0 + 8) * N + col0;
                v00 += r0[0]; v01 += r0[1]; v10 += r1[0]; v11 += r1[1];
            }
            float2 o0 = make_float2(v00, v01);
            float2 o1 = make_float2(v10, v11);
            *(float2*)(Cm + (size_t)row0 * N + col0)       = o0;
            *(float2*)(Cm + (size_t)(row0 + 8) * N + col0) = o1;
        }
    }
}

// ---------------------------------------------------------------------------
// LSH hashing: one warp per (b,h,s) position. Kahan-compensated dot so the
// bucket decision carries ~1e-8 noise (below the reference's own rounding).
// bucket = argmax concat(rotated,-rotated), first-occurrence tie-break.
// ---------------------------------------------------------------------------
__global__ void k_hash(const float* __restrict__ rot)
{
    int lane = threadIdx.x & 31;
    int wid  = blockIdx.x * (blockDim.x >> 5) + (threadIdx.x >> 5);
    if (wid >= BB * HH * SS) return;
    int b = wid / (HH * SS);
    int r = wid % (HH * SS);
    int h = r / SS;
    int s = r % SS;

    const float* q  = g_qk + ((size_t)(b * SS + s)) * DD + h * DHH;
    const float* rr = rot + (size_t)h * DHH * NROT;

    float sum = 0.f, comp = 0.f;
    #pragma unroll
    for (int d = 0; d < DHH; d++) {
        float p = __fmul_rn(q[d], rr[d * NROT + lane]);
        float y = __fsub_rn(p, comp);
        float t = __fadd_rn(sum, y);
        comp = __fsub_rn(__fsub_rn(t, sum), y);
        sum = t;
    }
    float acc = sum;

    float v; int idx;
    if (acc >= -acc) { v = acc;  idx = lane; }
    else             { v = -acc; idx = lane + NROT; }

    #pragma unroll
    for (int o = 16; o; o >>= 1) {
        float v2 = __shfl_down_sync(0xffffffffu, v, o);
        int   i2 = __shfl_down_sync(0xffffffffu, idx, o);
        if (v2 > v || (v2 == v && i2 < idx)) { v = v2; idx = i2; }
    }
    if (lane == 0) g_buckets[wid] = idx;
}

// ---------------------------------------------------------------------------
// Stable counting sort by bucket per (b,h): equivalent to
// argsort(bucket*S + pos).  One block of 64 threads per (b,h).
// ---------------------------------------------------------------------------
__global__ void k_sort()
{
    int bh = blockIdx.x;                 // 0..BB*HH-1
    const int* bk = g_buckets + (size_t)bh * SS;
    int* ord = g_order + (size_t)bh * SS;
    __shared__ int cnt[NBK], off[NBK];
    int t = threadIdx.x;                 // 0..63  == bucket id

    int c = 0;
    for (int s = 0; s < SS; s++)
        if (bk[s] == t) c++;
    cnt[t] = c;
    __syncthreads();
    if (t == 0) {
        int a = 0;
        for (int i = 0; i < NBK; i++) { off[i] = a; a += cnt[i]; }
    }
    __syncthreads();
    int o = off[t];
    for (int s = 0; s < SS; s++)
        if (bk[s] == t) ord[o++] = s;
}

// ---------------------------------------------------------------------------
// Gather into sorted order + key L2-normalization (exact fp32).
// One warp per position.
// ---------------------------------------------------------------------------
__global__ void k_gather(const int* __restrict__ mask)
{
    int lane = threadIdx.x & 31;
    int wid  = blockIdx.x * (blockDim.x >> 5) + (threadIdx.x >> 5);
    if (wid >= BB * HH * SS) return;
    int b = wid / (HH * SS);
    int r = wid % (HH * SS);
    int h = r / SS;

    int j = g_order[wid];
    const float* qrow = g_qk + ((size_t)(b * SS + j)) * DD + h * DHH;
    const float* vrow = g_v  + ((size_t)(b * SS + j)) * DD + h * DHH;

    float a0 = qrow[lane], a1 = qrow[lane + 32];
    float ss = a0 * a0 + a1 * a1;
    #pragma unroll
    for (int o = 16; o; o >>= 1) ss += __shfl_xor_sync(0xffffffffu, ss, o);
    float inv = __fdiv_rn(1.f, __fsqrt_rn(ss) + 1e-6f);

    size_t base = (size_t)wid * DHH;
    g_sqk [base + lane]      = a0;
    g_sqk [base + lane + 32] = a1;
    g_skey[base + lane]      = a0 * inv;
    g_skey[base + lane + 32] = a1 * inv;
    g_sv  [base + lane]      = vrow[lane];
    g_sv  [base + lane + 32] = vrow[lane + 32];

    if (lane == 0) {
        g_sb[wid] = g_buckets[(size_t)(b * HH + h) * SS + j];
        g_sm[wid] = mask[b * SS + j];
        g_si[wid] = j;
    }
}

// ---------------------------------------------------------------------------
// Chunked LSH attention: one block per (b,h,chunk). Keys/values look back
// one chunk (wraps). Masks + softmax + AV + unsort-scatter fused. Exact fp32;
// exp/div via accurate helpers (fast-math-proof).
// ---------------------------------------------------------------------------
#define ATTN_F (64*64 + 128*65 + 128*65 + 64*128)
#define ATTN_I (64 + 128 + 128 + 64 + 128)
#define ATTN_SMEM (ATTN_F*4 + ATTN_I*4)

__global__ void k_attn()
{
    extern __shared__ float smf[];
    float* qs = smf;                      // [64][64]
    float* ks = qs + 64 * 64;             // [128][65]
    float* vs = ks + 128 * 65;            // [128][65]
    float* ds = vs + 128 * 65;            // [64][128]
    int* ib = (int*)(ds + 64 * 128);
    int* bc = ib;            // [64]
    int* be = bc + 64;       // [128]
    int* me = be + 128;      // [128]
    int* ic = me + 128;      // [64]
    int* ie = ic + 64;       // [128]

    int n = blockIdx.x, h = blockIdx.y, b = blockIdx.z;
    int tid = threadIdx.x;                // 256 threads
    size_t base_bh = (size_t)(b * HH + h) * SS;
    int prev = (n + NCC - 1) % NCC;

    for (int idx = tid; idx < 64 * 64; idx += 256) {
        int c = idx >> 6, d = idx & 63;
        qs[idx] = g_sqk[(base_bh + n * CC + c) * DHH + d];
    }
    for (int idx = tid; idx < 128 * 64; idx += 256) {
        int k = idx >> 6, d = idx & 63;
        int chunk = (k < 64) ? prev : n;
        int rrow  = (k < 64) ? k : (k - 64);
        size_t src = (base_bh + chunk * CC + rrow) * DHH + d;
        ks[k * 65 + d] = g_skey[src];
        vs[k * 65 + d] = g_sv[src];
    }
    for (int idx = tid; idx < 64; idx += 256) {
        bc[idx] = g_sb[base_bh + n * CC + idx];
        ic[idx] = g_si[base_bh + n * CC + idx];
    }
    for (int idx = tid; idx < 128; idx += 256) {
        int chunk = (idx < 64) ? prev : n;
        int rrow  = (idx < 64) ? idx : (idx - 64);
        be[idx] = g_sb[base_bh + chunk * CC + rrow];
        me[idx] = g_sm[base_bh + chunk * CC + rrow];
        ie[idx] = g_si[base_bh + chunk * CC + rrow];
    }
    __syncthreads();

    // dots + masks
    for (int idx = tid; idx < 64 * 128; idx += 256) {
        int c = idx >> 7, k = idx & 127;
        float acc = 0.f;
        #pragma unroll
        for (int d = 0; d < 64; d++)
            acc += qs[c * 64 + d] * ks[k * 65 + d];
        acc *= 0.125f;                          // 1/sqrt(64), exact
        if (bc[c] != be[k] || me[k] <= 0) acc = -1e9f;
        if (ic[c] == ie[k])               acc = -1e5f;
        ds[c * 128 + k] = acc;
    }
    __syncthreads();

    // row softmax: 8 warps handle 64 rows
    int warp = tid >> 5, lane = tid & 31;
    for (int c = warp; c < 64; c += 8) {
        float v0 = ds[c * 128 + lane];
        float v1 = ds[c * 128 + lane + 32];
        float v2 = ds[c * 128 + lane + 64];
        float v3 = ds[c * 128 + lane + 96];
        float mx = fmaxf(fmaxf(v0, v1), fmaxf(v2, v3));
        #pragma unroll
        for (int o = 16; o; o >>= 1) mx = fmaxf(mx, __shfl_xor_sync(0xffffffffu, mx, o));
        float e0 = exp_acc(v0 - mx), e1 = exp_acc(v1 - mx);
        float e2 = exp_acc(v2 - mx), e3 = exp_acc(v3 - mx);
        float sm = e0 + e1 + e2 + e3;
        #pragma unroll
        for (int o = 16; o; o >>= 1) sm += __shfl_xor_sync(0xffffffffu, sm, o);
        ds[c * 128 + lane]      = __fdiv_rn(e0, sm);
        ds[c * 128 + lane + 32] = __fdiv_rn(e1, sm);
        ds[c * 128 + lane + 64] = __fdiv_rn(e2, sm);
        ds[c * 128 + lane + 96] = __fdiv_rn(e3, sm);
    }
    __syncthreads();

    // out = attn @ ve, scattered back to original positions (fused unsort)
    for (int idx = tid; idx < 64 * 64; idx += 256) {
        int c = idx >> 6, d = idx & 63;
        float acc = 0.f;
        #pragma unroll
        for (int k = 0; k < 128; k++)
            acc += ds[c * 128 + k] * vs[k * 65 + d];
        int sdst = ic[c];
        g_ao[((size_t)(b * SS + sdst)) * DD + h * DHH + d] = acc;
    }
}

// ---------------------------------------------------------------------------
// Launch
// ---------------------------------------------------------------------------
extern "C" void kernel_launch(void* const* d_in, const int* in_sizes, int n_in,
                              void* d_out, int out_size)
{
    const int*   ids  = (const int*)  d_in[0];
    const int*   mask = (const int*)  d_in[1];
    const float* emb  = (const float*)d_in[2];
    const float* pos  = (const float*)d_in[3];
    const float* rot  = (const float*)d_in[4];
    const float* Wqk  = (const float*)d_in[5];
    const float* Wv   = (const float*)d_in[6];
    const float* Wo   = (const float*)d_in[7];
    const float* ln1g = (const float*)d_in[8];
    const float* ln1b = (const float*)d_in[9];
    const float* ln2g = (const float*)d_in[10];
    const float* ln2b = (const float*)d_in[11];
    const float* W1   = (const float*)d_in[12];
    const float* b1   = (const float*)d_in[13];
    const float* W2   = (const float*)d_in[14];
    const float* b2   = (const float*)d_in[15];
    const float* lnfg = (const float*)d_in[16];
    const float* lnfb = (const float*)d_in[17];
    const float* Wlm  = (const float*)d_in[18];
    const float* blm  = (const float*)d_in[19];
    float* out = (float*)d_out;

    float *x, *h, *qk, *v, *ao, *ffn;
    cudaGetSymbolAddress((void**)&x,   g_x);
    cudaGetSymbolAddress((void**)&h,   g_h);
    cudaGetSymbolAddress((void**)&qk,  g_qk);
    cudaGetSymbolAddress((void**)&v,   g_v);
    cudaGetSymbolAddress((void**)&ao,  g_ao);
    cudaGetSymbolAddress((void**)&ffn, g_ffn);

    cudaFuncSetAttribute(k_attn, cudaFuncAttributeMaxDynamicSharedMemorySize, ATTN_SMEM);

    k_embed<<<MM, 256>>>(ids, emb, pos);

    dim3 gD (DD / 128,  MM / 128);
    dim3 gF (FF / 128,  MM / 128);
    dim3 gV (VV / 128,  MM / 128);

    // ---------------- layer 0: fully exact (feeds layer-1 AND layer-2 buckets)
    {
        int l = 0;
        k_ln<<<MM, 256>>>(x, h, ln1g + l * DD, ln1b + l * DD);
        k_gemm<EPI_NONE><<<gD, 256>>>(h, Wqk + (size_t)l * DD * DD, nullptr, nullptr, qk, MM, DD, DD);
        k_gemm<EPI_NONE><<<gD, 256>>>(h, Wv  + (size_t)l * DD * DD, nullptr, nullptr, v,  MM, DD, DD);
        k_hash<<<(BB * HH * SS) / 4, 128>>>(rot + (size_t)l * HH * DHH * NROT);
        k_sort<<<BB * HH, NBK>>>();
        k_gather<<<(BB * HH * SS) / 4, 128>>>(mask);
        k_attn<<<dim3(NCC, HH, BB), 256, ATTN_SMEM>>>();
        k_gemm<EPI_RES><<<gD, 256>>>(ao, Wo + (size_t)l * DD * DD, nullptr, x, x, MM, DD, DD);
        k_ln<<<MM, 256>>>(x, h, ln2g + l * DD, ln2b + l * DD);
        k_gemm<EPI_BIAS_GELU><<<gF, 256>>>(h, W1 + (size_t)l * DD * FF, b1 + (size_t)l * FF, nullptr, ffn, MM, FF, DD);
        k_gemm<EPI_BIAS_RES><<<gD, 256>>>(ffn, W2 + (size_t)l * FF * DD, b2 + (size_t)l * DD, x, x, MM, DD, FF);
    }

    // ---------------- layer 1: Wqk exact (feeds buckets); everything after the
    // hash is continuous -> fast 3xTF32 tensor-core path
    {
        int l = 1;
        k_ln<<<MM, 256>>>(x, h, ln1g + l * DD, ln1b + l * DD);
        k_gemm<EPI_NONE><<<gD, 256>>>(h, Wqk + (size_t)l * DD * DD, nullptr, nullptr, qk, MM, DD, DD);
        k_gemm_tf32<EPI_NONE><<<gD, 256>>>(h, Wv + (size_t)l * DD * DD, nullptr, nullptr, v, MM, DD, DD);
        k_hash<<<(BB * HH * SS) / 4, 128>>>(rot + (size_t)l * HH * DHH * NROT);
        k_sort<<<BB * HH, NBK>>>();
        k_gather<<<(BB * HH * SS) / 4, 128>>>(mask);
        k_attn<<<dim3(NCC, HH, BB), 256, ATTN_SMEM>>>();
        k_gemm_tf32<EPI_RES><<<gD, 256>>>(ao, Wo + (size_t)l * DD * DD, nullptr, x, x, MM, DD, DD);
        k_ln<<<MM, 256>>>(x, h, ln2g + l * DD, ln2b + l * DD);
        k_gemm_tf32<EPI_BIAS_GELU><<<gF, 256>>>(h, W1 + (size_t)l * DD * FF, b1 + (size_t)l * FF, nullptr, ffn, MM, FF, DD);
        k_gemm_tf32<EPI_BIAS_RES><<<gD, 256>>>(ffn, W2 + (size_t)l * FF * DD, b2 + (size_t)l * DD, x, x, MM, DD, FF);
    }

    k_ln<<<MM, 256>>>(x, h, lnfg, lnfb);
    k_gemm_tf32<EPI_BIAS><<<gV, 256>>>(h, Wlm, blm, nullptr, out, MM, VV, DD);
}